// round 4
// baseline (speedup 1.0000x reference)
#include <cuda_runtime.h>

#define NN 50000
#define NE 800000
#define FULLMASK 0xffffffffu

// ---------------- static device scratch (no allocation allowed) ----------------
__device__ float d_Q [NN * 128];
__device__ float d_Kn[NN * 128];
__device__ float d_Vn[NN * 128];
__device__ float d_Ov[NN * 128];
__device__ __align__(16) int d_deg[NN];
__device__ int   d_cur[NN];
__device__ __align__(16) int d_rowptr[NN + 4];
__device__ int   d_eperm[NE];
__device__ int   d_srcp [NE];

// ---------------- CSR build ----------------
__global__ void zero_kernel(int n) {
    int i = blockIdx.x * blockDim.x + threadIdx.x;
    if (i < n) { d_deg[i] = 0; d_cur[i] = 0; }
}

__global__ void deg_kernel(const int* __restrict__ tgt, int E) {
    int e = blockIdx.x * blockDim.x + threadIdx.x;
    if (e < E) atomicAdd(&d_deg[tgt[e]], 1);
}

// single-block exclusive scan of d_deg -> d_rowptr, int4-vectorized
__global__ void scan_kernel(int n) {
    __shared__ int ssum[1024];
    int t = threadIdx.x;
    int n4 = n >> 2;                       // whole int4s
    int C = (n4 + 1023) >> 10;
    int s0 = t * C;
    int s1 = min(s0 + C, n4);
    const int4* deg4 = (const int4*)d_deg;
    int s = 0;
    for (int i = s0; i < s1; i++) {
        int4 v = deg4[i];
        s += v.x + v.y + v.z + v.w;
    }
    ssum[t] = s;
    __syncthreads();
    for (int off = 1; off < 1024; off <<= 1) {
        int v = 0;
        if (t >= off) v = ssum[t - off];
        __syncthreads();
        if (t >= off) ssum[t] += v;
        __syncthreads();
    }
    int run = (t == 0) ? 0 : ssum[t - 1];
    int4* rp4 = (int4*)d_rowptr;
    for (int i = s0; i < s1; i++) {
        int4 v = deg4[i];
        int4 r;
        r.x = run; run += v.x;
        r.y = run; run += v.y;
        r.z = run; run += v.z;
        r.w = run; run += v.w;
        rp4[i] = r;
    }
    if (t == 1023) {
        int run2 = ssum[1023];
        for (int i = n4 * 4; i < n; i++) { d_rowptr[i] = run2; run2 += d_deg[i]; }
        d_rowptr[n] = run2;
    }
}

__global__ void scatter_kernel(const int* __restrict__ src, const int* __restrict__ tgt, int E) {
    int e = blockIdx.x * blockDim.x + threadIdx.x;
    if (e < E) {
        int tg = tgt[e];
        int pos = d_rowptr[tg] + atomicAdd(&d_cur[tg], 1);
        d_eperm[pos] = e;
        d_srcp[pos]  = src[e];
    }
}

// ---------------- fp32 tiled GEMM body: C[M,128] = A[M,128] @ B[:128,128] + bias ----------------
// double-buffered smem, one __syncthreads per k-step, LDG prefetch overlapped with FMA
__device__ __forceinline__ void gemm_body(const float* __restrict__ A,
                                          const float* __restrict__ B,
                                          const float* __restrict__ bias,
                                          float* __restrict__ C, int M, int bm)
{
    __shared__ float As[2][8][132];
    __shared__ float Bs[2][8][128];
    int tid = threadIdx.x;
    int tx = tid & 15;            // col group
    int ty = tid >> 4;            // row group
    int c0 = tx * 8, r0 = ty * 8;
    float acc[8][8];
#pragma unroll
    for (int i = 0; i < 8; i++)
#pragma unroll
        for (int j = 0; j < 8; j++) acc[i][j] = 0.f;

    int a_row = tid >> 1;          // 0..127
    int a_k   = (tid & 1) * 4;     // 0 or 4
    int b_k   = tid >> 5;          // 0..7
    int b_c   = (tid & 31) * 4;    // 0..124

    int ar = bm + a_row; if (ar >= M) ar = M - 1;
    const float* Aptr = A + (size_t)ar * 128 + a_k;
    const float* Bptr = B + (size_t)b_k * 128 + b_c;

    // preload k0 = 0
    {
        float4 av = *(const float4*)(Aptr);
        float4 bv = *(const float4*)(Bptr);
        As[0][a_k + 0][a_row] = av.x;
        As[0][a_k + 1][a_row] = av.y;
        As[0][a_k + 2][a_row] = av.z;
        As[0][a_k + 3][a_row] = av.w;
        *(float4*)&Bs[0][b_k][b_c] = bv;
    }
    __syncthreads();

    int buf = 0;
    for (int k0 = 0; k0 < 128; k0 += 8) {
        bool has_next = (k0 + 8) < 128;
        float4 av2, bv2;
        if (has_next) {
            av2 = *(const float4*)(Aptr + k0 + 8);
            bv2 = *(const float4*)(Bptr + (size_t)(k0 + 8) * 128);
        }
#pragma unroll
        for (int k = 0; k < 8; k++) {
            float4 a0 = *(const float4*)&As[buf][k][r0];
            float4 a1 = *(const float4*)&As[buf][k][r0 + 4];
            float4 b0 = *(const float4*)&Bs[buf][k][c0];
            float4 b1 = *(const float4*)&Bs[buf][k][c0 + 4];
            float aa[8] = {a0.x, a0.y, a0.z, a0.w, a1.x, a1.y, a1.z, a1.w};
            float bb[8] = {b0.x, b0.y, b0.z, b0.w, b1.x, b1.y, b1.z, b1.w};
#pragma unroll
            for (int i = 0; i < 8; i++)
#pragma unroll
                for (int j = 0; j < 8; j++)
                    acc[i][j] += aa[i] * bb[j];
        }
        if (has_next) {
            int nb = buf ^ 1;
            As[nb][a_k + 0][a_row] = av2.x;
            As[nb][a_k + 1][a_row] = av2.y;
            As[nb][a_k + 2][a_row] = av2.z;
            As[nb][a_k + 3][a_row] = av2.w;
            *(float4*)&Bs[nb][b_k][b_c] = bv2;
            __syncthreads();
            buf = nb;
        }
    }
    float4 bias0 = *(const float4*)(bias + c0);
    float4 bias1 = *(const float4*)(bias + c0 + 4);
    float bb[8] = {bias0.x, bias0.y, bias0.z, bias0.w, bias1.x, bias1.y, bias1.z, bias1.w};
#pragma unroll
    for (int i = 0; i < 8; i++) {
        int row = bm + r0 + i;
        if (row < M) {
            float4 o0 = {acc[i][0] + bb[0], acc[i][1] + bb[1], acc[i][2] + bb[2], acc[i][3] + bb[3]};
            float4 o1 = {acc[i][4] + bb[4], acc[i][5] + bb[5], acc[i][6] + bb[6], acc[i][7] + bb[7]};
            *(float4*)(C + (size_t)row * 128 + c0)     = o0;
            *(float4*)(C + (size_t)row * 128 + c0 + 4) = o1;
        }
    }
}

__global__ void __launch_bounds__(256) gemm_k128(const float* __restrict__ A,
                                                 const float* __restrict__ B,
                                                 const float* __restrict__ bias,
                                                 float* __restrict__ C, int M)
{
    gemm_body(A, B, bias, C, M, blockIdx.x * 128);
}

// fused Q/K/V projection: blockIdx.y selects which output (0=Q,1=K,2=V)
__global__ void __launch_bounds__(256) gemm_qkv(const float* __restrict__ A,
                                                const float* __restrict__ Wq,
                                                const float* __restrict__ bq,
                                                const float* __restrict__ Wk,
                                                const float* __restrict__ bk,
                                                const float* __restrict__ Wv,
                                                const float* __restrict__ bv,
                                                float* __restrict__ Q,
                                                float* __restrict__ K,
                                                float* __restrict__ V, int M)
{
    const float* B;  const float* bias;  float* C;
    if (blockIdx.y == 0)      { B = Wq; bias = bq; C = Q; }
    else if (blockIdx.y == 1) { B = Wk; bias = bk; C = K; }   // rows 0..127 of Wk
    else                      { B = Wv; bias = bv; C = V; }   // rows 0..127 of Wv
    gemm_body(A, B, bias, C, M, blockIdx.x * 128);
}

// ---------------- fused per-node attention (warp per node, CSR) ----------------
// Lane layout: lane owns channels [4*lane, 4*lane+4) -> head h = lane>>2,
// and edge-feature dims [16*(lane&3), +16). Quad (4 lanes) = one head.
// Edge loop is software-pipelined: next edge's gathers issued before current compute.
__global__ void __launch_bounds__(256) attn_kernel(const float* __restrict__ edge_feats,
                                                   const float* __restrict__ Wk,
                                                   const float* __restrict__ Wv,
                                                   int N)
{
    __shared__ float Wve[64 * 128];   // Wv rows 128..191 (edge part), 32 KB
    int tid = threadIdx.x;
    {
        const float4* s2 = (const float4*)(Wv + 128 * 128);
        float4* dst = (float4*)Wve;
        for (int i = tid; i < 2048; i += blockDim.x) dst[i] = s2[i];
    }
    __syncthreads();

    int lane = tid & 31;
    int warp = tid >> 5;
    int cb = lane * 4;            // channel base
    int h  = lane >> 2;           // head
    int d0 = (lane & 3) * 16;     // edge-dim base
    int qb = lane & ~3;           // quad base lane

    int gw = blockIdx.x * (blockDim.x >> 5) + warp;
    int nw = gridDim.x * (blockDim.x >> 5);

    for (int n = gw; n < N; n += nw) {
        int beg = d_rowptr[n], end = d_rowptr[n + 1];
        float4 q = *(const float4*)(d_Q + (size_t)n * 128 + cb);

        // gather all 16 q values of this head via quad shuffles
        float qh[16];
#pragma unroll
        for (int t = 0; t < 4; t++) {
            qh[4 * t + 0] = __shfl_sync(FULLMASK, q.x, qb + t);
            qh[4 * t + 1] = __shfl_sync(FULLMASK, q.y, qb + t);
            qh[4 * t + 2] = __shfl_sync(FULLMASK, q.z, qb + t);
            qh[4 * t + 3] = __shfl_sync(FULLMASK, q.w, qb + t);
        }
        // U[j] = sum_c qh[c] * Wk_e[d0+j][16h+c]   (Wk_e global, L1-resident)
        float U[16];
#pragma unroll
        for (int j = 0; j < 16; j++) {
            const float4* w = (const float4*)(Wk + (size_t)(128 + d0 + j) * 128 + h * 16);
            float4 w0 = w[0], w1 = w[1], w2 = w[2], w3 = w[3];
            U[j] = qh[0]  * w0.x + qh[1]  * w0.y + qh[2]  * w0.z + qh[3]  * w0.w
                 + qh[4]  * w1.x + qh[5]  * w1.y + qh[6]  * w1.z + qh[7]  * w1.w
                 + qh[8]  * w2.x + qh[9]  * w2.y + qh[10] * w2.z + qh[11] * w2.w
                 + qh[12] * w3.x + qh[13] * w3.y + qh[14] * w3.z + qh[15] * w3.w;
        }

        float g[16];
#pragma unroll
        for (int j = 0; j < 16; j++) g[j] = 0.f;
        float o0 = 0.f, o1 = 0.f, o2 = 0.f, o3 = 0.f, sacc = 0.f;

        // --- software-pipelined edge loop ---
        float4 ce0, ce1, ce2, ce3, ckn, cvn;
        int idx = beg;
        if (idx < end) {
            int e = d_eperm[idx];
            int s = d_srcp[idx];
            const float4* ef = (const float4*)(edge_feats + (size_t)e * 64 + d0);
            ce0 = ef[0]; ce1 = ef[1]; ce2 = ef[2]; ce3 = ef[3];
            ckn = *(const float4*)(d_Kn + (size_t)s * 128 + cb);
            cvn = *(const float4*)(d_Vn + (size_t)s * 128 + cb);
        }
        while (idx < end) {
            int nidx = idx + 1;
            float4 ne0, ne1, ne2, ne3, nkn, nvn;
            if (nidx < end) {
                int e = d_eperm[nidx];
                int s = d_srcp[nidx];
                const float4* ef = (const float4*)(edge_feats + (size_t)e * 64 + d0);
                ne0 = ef[0]; ne1 = ef[1]; ne2 = ef[2]; ne3 = ef[3];
                nkn = *(const float4*)(d_Kn + (size_t)s * 128 + cb);
                nvn = *(const float4*)(d_Vn + (size_t)s * 128 + cb);
            }
            float part = q.x * ckn.x + q.y * ckn.y + q.z * ckn.z + q.w * ckn.w;
            part += ce0.x * U[0]  + ce0.y * U[1]  + ce0.z * U[2]  + ce0.w * U[3];
            part += ce1.x * U[4]  + ce1.y * U[5]  + ce1.z * U[6]  + ce1.w * U[7];
            part += ce2.x * U[8]  + ce2.y * U[9]  + ce2.z * U[10] + ce2.w * U[11];
            part += ce3.x * U[12] + ce3.y * U[13] + ce3.z * U[14] + ce3.w * U[15];
            part += __shfl_xor_sync(FULLMASK, part, 1);
            part += __shfl_xor_sync(FULLMASK, part, 2);   // full head logit in all 4 lanes
            float p = __expf(0.25f * part);
            sacc += p;
            o0 += p * cvn.x; o1 += p * cvn.y; o2 += p * cvn.z; o3 += p * cvn.w;
            g[0]  += p * ce0.x; g[1]  += p * ce0.y; g[2]  += p * ce0.z; g[3]  += p * ce0.w;
            g[4]  += p * ce1.x; g[5]  += p * ce1.y; g[6]  += p * ce1.z; g[7]  += p * ce1.w;
            g[8]  += p * ce2.x; g[9]  += p * ce2.y; g[10] += p * ce2.z; g[11] += p * ce2.w;
            g[12] += p * ce3.x; g[13] += p * ce3.y; g[14] += p * ce3.z; g[15] += p * ce3.w;
            ce0 = ne0; ce1 = ne1; ce2 = ne2; ce3 = ne3; ckn = nkn; cvn = nvn;
            idx = nidx;
        }

        // epilogue: o += g @ Wv_e   (g distributed over the quad; exchange via shuffles)
        float ep0 = 0.f, ep1 = 0.f, ep2 = 0.f, ep3 = 0.f;
#pragma unroll
        for (int t = 0; t < 4; t++) {
#pragma unroll
            for (int j = 0; j < 16; j++) {
                float gv = __shfl_sync(FULLMASK, g[j], qb + t);
                float4 w = *(const float4*)(Wve + (size_t)(t * 16 + j) * 128 + cb);
                ep0 += gv * w.x; ep1 += gv * w.y; ep2 += gv * w.z; ep3 += gv * w.w;
            }
        }
        float inv = (sacc > 0.f) ? (1.0f / sacc) : 0.f;
        float4 res;
        res.x = (o0 + ep0) * inv;
        res.y = (o1 + ep1) * inv;
        res.z = (o2 + ep2) * inv;
        res.w = (o3 + ep3) * inv;
        *(float4*)(d_Ov + (size_t)n * 128 + cb) = res;
    }
}

// ---------------- host launcher ----------------
extern "C" void kernel_launch(void* const* d_in, const int* in_sizes, int n_in,
                              void* d_out, int out_size)
{
    const float* node_feats = (const float*)d_in[0];
    const float* edge_feats = (const float*)d_in[1];
    const int*   edge_index = (const int*)  d_in[2];
    const float* Wq = (const float*)d_in[3];
    const float* bq = (const float*)d_in[4];
    const float* Wk = (const float*)d_in[5];
    const float* bk = (const float*)d_in[6];
    const float* Wv = (const float*)d_in[7];
    const float* bv = (const float*)d_in[8];
    const float* Wo = (const float*)d_in[9];
    const float* bo = (const float*)d_in[10];
    float* out = (float*)d_out;

    int N = in_sizes[0] / 128;
    int E = in_sizes[1] / 64;
    const int* src = edge_index;
    const int* tgt = edge_index + E;

    float *pQ, *pKn, *pVn, *pO;
    cudaGetSymbolAddress((void**)&pQ,  d_Q);
    cudaGetSymbolAddress((void**)&pKn, d_Kn);
    cudaGetSymbolAddress((void**)&pVn, d_Vn);
    cudaGetSymbolAddress((void**)&pO,  d_Ov);

    int gblocks = (N + 127) / 128;

    zero_kernel<<<(N + 255) / 256, 256>>>(N);
    gemm_qkv<<<dim3(gblocks, 3), 256>>>(node_feats, Wq, bq, Wk, bk, Wv, bv, pQ, pKn, pVn, N);
    deg_kernel<<<(E + 255) / 256, 256>>>(tgt, E);
    scan_kernel<<<1, 1024>>>(N);
    scatter_kernel<<<(E + 255) / 256, 256>>>(src, tgt, E);
    attn_kernel<<<888, 256>>>(edge_feats, Wk, Wv, N);
    gemm_k128<<<gblocks, 256>>>(pO, Wo, bo, out, N);
}

// round 5
// speedup vs baseline: 1.1234x; 1.1234x over previous
#include <cuda_runtime.h>

#define NN 50000
#define NE 800000
#define FULLMASK 0xffffffffu

// ---------------- static device scratch (no allocation allowed) ----------------
__device__ float d_Q [NN * 128];
__device__ float d_Kn[NN * 128];
__device__ float d_Vn[NN * 128];
__device__ float d_Ov[NN * 128];
__device__ float d_efp[(size_t)NE * 64];   // edge feats permuted into CSR order (205MB)
__device__ __align__(16) int d_deg[NN];
__device__ int   d_cur[NN];
__device__ __align__(16) int d_rowptr[NN + 4];
__device__ int   d_pos [NE];               // CSR slot of edge e
__device__ int   d_srcp[NE];               // source node per CSR slot

// ---------------- CSR build ----------------
__global__ void zero_kernel(int n) {
    int i = blockIdx.x * blockDim.x + threadIdx.x;
    if (i < n) { d_deg[i] = 0; d_cur[i] = 0; }
}

__global__ void deg_kernel(const int* __restrict__ tgt, int E) {
    int e = blockIdx.x * blockDim.x + threadIdx.x;
    if (e < E) atomicAdd(&d_deg[tgt[e]], 1);
}

// single-block exclusive scan of d_deg -> d_rowptr, int4-vectorized
__global__ void scan_kernel(int n) {
    __shared__ int ssum[1024];
    int t = threadIdx.x;
    int n4 = n >> 2;
    int C = (n4 + 1023) >> 10;
    int s0 = t * C;
    int s1 = min(s0 + C, n4);
    const int4* deg4 = (const int4*)d_deg;
    int s = 0;
    for (int i = s0; i < s1; i++) {
        int4 v = deg4[i];
        s += v.x + v.y + v.z + v.w;
    }
    ssum[t] = s;
    __syncthreads();
    for (int off = 1; off < 1024; off <<= 1) {
        int v = 0;
        if (t >= off) v = ssum[t - off];
        __syncthreads();
        if (t >= off) ssum[t] += v;
        __syncthreads();
    }
    int run = (t == 0) ? 0 : ssum[t - 1];
    int4* rp4 = (int4*)d_rowptr;
    for (int i = s0; i < s1; i++) {
        int4 v = deg4[i];
        int4 r;
        r.x = run; run += v.x;
        r.y = run; run += v.y;
        r.z = run; run += v.z;
        r.w = run; run += v.w;
        rp4[i] = r;
    }
    if (t == 1023) {
        int run2 = ssum[1023];
        for (int i = n4 * 4; i < n; i++) { d_rowptr[i] = run2; run2 += d_deg[i]; }
        d_rowptr[n] = run2;
    }
}

__global__ void scatter_kernel(const int* __restrict__ src, const int* __restrict__ tgt, int E) {
    int e = blockIdx.x * blockDim.x + threadIdx.x;
    if (e < E) {
        int tg = tgt[e];
        int pos = d_rowptr[tg] + atomicAdd(&d_cur[tg], 1);
        d_pos[e]    = pos;
        d_srcp[pos] = src[e];
    }
}

// permute edge features into CSR order: one warp per edge, float2 per lane (256B line)
__global__ void __launch_bounds__(256) copy_ef_kernel(const float* __restrict__ edge_feats, int E) {
    int w = (blockIdx.x * blockDim.x + threadIdx.x) >> 5;
    int lane = threadIdx.x & 31;
    if (w < E) {
        int pos = d_pos[w];
        const float2* srcp = (const float2*)(edge_feats + (size_t)w * 64);
        float2 v = srcp[lane];
        ((float2*)(d_efp + (size_t)pos * 64))[lane] = v;
    }
}

// ---------------- fp32 tiled GEMM body (R3-measured form, single buffer) ----------------
__device__ __forceinline__ void gemm_body(const float* __restrict__ A,
                                          const float* __restrict__ B,
                                          const float* __restrict__ bias,
                                          float* __restrict__ C, int M, int bm)
{
    __shared__ float As[8][132];
    __shared__ float Bs[8][128];
    int tid = threadIdx.x;
    int tx = tid & 15;
    int ty = tid >> 4;
    int c0 = tx * 8, r0 = ty * 8;
    float acc[8][8];
#pragma unroll
    for (int i = 0; i < 8; i++)
#pragma unroll
        for (int j = 0; j < 8; j++) acc[i][j] = 0.f;

    int a_row = tid >> 1;
    int a_k   = (tid & 1) * 4;
    int b_k   = tid >> 5;
    int b_c   = (tid & 31) * 4;

    for (int k0 = 0; k0 < 128; k0 += 8) {
        int ar = bm + a_row; if (ar >= M) ar = M - 1;
        float4 av = *(const float4*)(A + (size_t)ar * 128 + k0 + a_k);
        As[a_k + 0][a_row] = av.x;
        As[a_k + 1][a_row] = av.y;
        As[a_k + 2][a_row] = av.z;
        As[a_k + 3][a_row] = av.w;
        float4 bv = *(const float4*)(B + (size_t)(k0 + b_k) * 128 + b_c);
        *(float4*)&Bs[b_k][b_c] = bv;
        __syncthreads();
#pragma unroll
        for (int k = 0; k < 8; k++) {
            float4 a0 = *(const float4*)&As[k][r0];
            float4 a1 = *(const float4*)&As[k][r0 + 4];
            float4 b0 = *(const float4*)&Bs[k][c0];
            float4 b1 = *(const float4*)&Bs[k][c0 + 4];
            float aa[8] = {a0.x, a0.y, a0.z, a0.w, a1.x, a1.y, a1.z, a1.w};
            float bb[8] = {b0.x, b0.y, b0.z, b0.w, b1.x, b1.y, b1.z, b1.w};
#pragma unroll
            for (int i = 0; i < 8; i++)
#pragma unroll
                for (int j = 0; j < 8; j++)
                    acc[i][j] += aa[i] * bb[j];
        }
        __syncthreads();
    }
    float4 bias0 = *(const float4*)(bias + c0);
    float4 bias1 = *(const float4*)(bias + c0 + 4);
    float bb[8] = {bias0.x, bias0.y, bias0.z, bias0.w, bias1.x, bias1.y, bias1.z, bias1.w};
#pragma unroll
    for (int i = 0; i < 8; i++) {
        int row = bm + r0 + i;
        if (row < M) {
            float4 o0 = {acc[i][0] + bb[0], acc[i][1] + bb[1], acc[i][2] + bb[2], acc[i][3] + bb[3]};
            float4 o1 = {acc[i][4] + bb[4], acc[i][5] + bb[5], acc[i][6] + bb[6], acc[i][7] + bb[7]};
            *(float4*)(C + (size_t)row * 128 + c0)     = o0;
            *(float4*)(C + (size_t)row * 128 + c0 + 4) = o1;
        }
    }
}

__global__ void __launch_bounds__(256) gemm_k128(const float* __restrict__ A,
                                                 const float* __restrict__ B,
                                                 const float* __restrict__ bias,
                                                 float* __restrict__ C, int M)
{
    gemm_body(A, B, bias, C, M, blockIdx.x * 128);
}

__global__ void __launch_bounds__(256) gemm_qkv(const float* __restrict__ A,
                                                const float* __restrict__ Wq,
                                                const float* __restrict__ bq,
                                                const float* __restrict__ Wk,
                                                const float* __restrict__ bk,
                                                const float* __restrict__ Wv,
                                                const float* __restrict__ bv,
                                                float* __restrict__ Q,
                                                float* __restrict__ K,
                                                float* __restrict__ V, int M)
{
    const float* B;  const float* bias;  float* C;
    if (blockIdx.y == 0)      { B = Wq; bias = bq; C = Q; }
    else if (blockIdx.y == 1) { B = Wk; bias = bk; C = K; }
    else                      { B = Wv; bias = bv; C = V; }
    gemm_body(A, B, bias, C, M, blockIdx.x * 128);
}

// ---------------- fused per-node attention (warp per node, CSR) ----------------
// Lane layout: lane owns channels [4*lane,4*lane+4) -> head h = lane>>2,
// and edge-feature dims [16*(lane&3), +16). Quad (4 lanes) = one head.
// Edge features are pre-permuted into CSR order (d_efp) -> sequential reads,
// no per-edge indirection for ef. Simple loop: ptxas front-batches the LDGs.
__global__ void __launch_bounds__(256) attn_kernel(const float* __restrict__ Wk,
                                                   const float* __restrict__ Wv,
                                                   int N)
{
    __shared__ float Wve[64 * 128];   // Wv rows 128..191 (edge part), 32 KB
    int tid = threadIdx.x;
    {
        const float4* s2 = (const float4*)(Wv + 128 * 128);
        float4* dst = (float4*)Wve;
        for (int i = tid; i < 2048; i += blockDim.x) dst[i] = s2[i];
    }
    __syncthreads();

    int lane = tid & 31;
    int warp = tid >> 5;
    int cb = lane * 4;
    int h  = lane >> 2;
    int d0 = (lane & 3) * 16;
    int qb = lane & ~3;

    int gw = blockIdx.x * (blockDim.x >> 5) + warp;
    int nw = gridDim.x * (blockDim.x >> 5);

    for (int n = gw; n < N; n += nw) {
        int beg = d_rowptr[n], end = d_rowptr[n + 1];
        float4 q = *(const float4*)(d_Q + (size_t)n * 128 + cb);

        float qh[16];
#pragma unroll
        for (int t = 0; t < 4; t++) {
            qh[4 * t + 0] = __shfl_sync(FULLMASK, q.x, qb + t);
            qh[4 * t + 1] = __shfl_sync(FULLMASK, q.y, qb + t);
            qh[4 * t + 2] = __shfl_sync(FULLMASK, q.z, qb + t);
            qh[4 * t + 3] = __shfl_sync(FULLMASK, q.w, qb + t);
        }
        float U[16];
#pragma unroll
        for (int j = 0; j < 16; j++) {
            const float4* w = (const float4*)(Wk + (size_t)(128 + d0 + j) * 128 + h * 16);
            float4 w0 = w[0], w1 = w[1], w2 = w[2], w3 = w[3];
            U[j] = qh[0]  * w0.x + qh[1]  * w0.y + qh[2]  * w0.z + qh[3]  * w0.w
                 + qh[4]  * w1.x + qh[5]  * w1.y + qh[6]  * w1.z + qh[7]  * w1.w
                 + qh[8]  * w2.x + qh[9]  * w2.y + qh[10] * w2.z + qh[11] * w2.w
                 + qh[12] * w3.x + qh[13] * w3.y + qh[14] * w3.z + qh[15] * w3.w;
        }

        float g[16];
#pragma unroll
        for (int j = 0; j < 16; j++) g[j] = 0.f;
        float o0 = 0.f, o1 = 0.f, o2 = 0.f, o3 = 0.f, sacc = 0.f;

        for (int idx = beg; idx < end; idx++) {
            int s = d_srcp[idx];
            const float4* ef = (const float4*)(d_efp + (size_t)idx * 64 + d0);
            float4 e0 = ef[0], e1 = ef[1], e2 = ef[2], e3 = ef[3];
            float4 kn = *(const float4*)(d_Kn + (size_t)s * 128 + cb);
            float part = q.x * kn.x + q.y * kn.y + q.z * kn.z + q.w * kn.w;
            part += e0.x * U[0]  + e0.y * U[1]  + e0.z * U[2]  + e0.w * U[3];
            part += e1.x * U[4]  + e1.y * U[5]  + e1.z * U[6]  + e1.w * U[7];
            part += e2.x * U[8]  + e2.y * U[9]  + e2.z * U[10] + e2.w * U[11];
            part += e3.x * U[12] + e3.y * U[13] + e3.z * U[14] + e3.w * U[15];
            part += __shfl_xor_sync(FULLMASK, part, 1);
            part += __shfl_xor_sync(FULLMASK, part, 2);
            float p = __expf(0.25f * part);
            sacc += p;
            float4 vn = *(const float4*)(d_Vn + (size_t)s * 128 + cb);
            o0 += p * vn.x; o1 += p * vn.y; o2 += p * vn.z; o3 += p * vn.w;
            g[0]  += p * e0.x; g[1]  += p * e0.y; g[2]  += p * e0.z; g[3]  += p * e0.w;
            g[4]  += p * e1.x; g[5]  += p * e1.y; g[6]  += p * e1.z; g[7]  += p * e1.w;
            g[8]  += p * e2.x; g[9]  += p * e2.y; g[10] += p * e2.z; g[11] += p * e2.w;
            g[12] += p * e3.x; g[13] += p * e3.y; g[14] += p * e3.z; g[15] += p * e3.w;
        }

        float ep0 = 0.f, ep1 = 0.f, ep2 = 0.f, ep3 = 0.f;
#pragma unroll
        for (int t = 0; t < 4; t++) {
#pragma unroll
            for (int j = 0; j < 16; j++) {
                float gv = __shfl_sync(FULLMASK, g[j], qb + t);
                float4 w = *(const float4*)(Wve + (size_t)(t * 16 + j) * 128 + cb);
                ep0 += gv * w.x; ep1 += gv * w.y; ep2 += gv * w.z; ep3 += gv * w.w;
            }
        }
        float inv = (sacc > 0.f) ? (1.0f / sacc) : 0.f;
        float4 res;
        res.x = (o0 + ep0) * inv;
        res.y = (o1 + ep1) * inv;
        res.z = (o2 + ep2) * inv;
        res.w = (o3 + ep3) * inv;
        *(float4*)(d_Ov + (size_t)n * 128 + cb) = res;
    }
}

// ---------------- host launcher ----------------
extern "C" void kernel_launch(void* const* d_in, const int* in_sizes, int n_in,
                              void* d_out, int out_size)
{
    const float* node_feats = (const float*)d_in[0];
    const float* edge_feats = (const float*)d_in[1];
    const int*   edge_index = (const int*)  d_in[2];
    const float* Wq = (const float*)d_in[3];
    const float* bq = (const float*)d_in[4];
    const float* Wk = (const float*)d_in[5];
    const float* bk = (const float*)d_in[6];
    const float* Wv = (const float*)d_in[7];
    const float* bv = (const float*)d_in[8];
    const float* Wo = (const float*)d_in[9];
    const float* bo = (const float*)d_in[10];
    float* out = (float*)d_out;

    int N = in_sizes[0] / 128;
    int E = in_sizes[1] / 64;
    const int* src = edge_index;
    const int* tgt = edge_index + E;

    float *pQ, *pKn, *pVn, *pO;
    cudaGetSymbolAddress((void**)&pQ,  d_Q);
    cudaGetSymbolAddress((void**)&pKn, d_Kn);
    cudaGetSymbolAddress((void**)&pVn, d_Vn);
    cudaGetSymbolAddress((void**)&pO,  d_Ov);

    int gblocks = (N + 127) / 128;

    zero_kernel<<<(N + 255) / 256, 256>>>(N);
    deg_kernel<<<(E + 255) / 256, 256>>>(tgt, E);
    scan_kernel<<<1, 1024>>>(N);
    scatter_kernel<<<(E + 255) / 256, 256>>>(src, tgt, E);
    copy_ef_kernel<<<(E * 32 + 255) / 256, 256>>>(edge_feats, E);
    gemm_qkv<<<dim3(gblocks, 3), 256>>>(node_feats, Wq, bq, Wk, bk, Wv, bv, pQ, pKn, pVn, N);
    attn_kernel<<<888, 256>>>(Wk, Wv, N);
    gemm_k128<<<gblocks, 256>>>(pO, Wo, bo, out, N);
}

// round 7
// speedup vs baseline: 1.3444x; 1.1968x over previous
#include <cuda_runtime.h>

#define NN 50000
#define NE 800000
#define FULLMASK 0xffffffffu

// ---------------- static device scratch (no allocation allowed) ----------------
__device__ float d_Q [NN * 128];
__device__ float d_Kn[NN * 128];
__device__ float d_Vn[NN * 128];
__device__ float d_Ov[NN * 128];
__device__ __align__(16) int d_deg[NN];
__device__ int   d_cur[NN];
__device__ __align__(16) int d_rowptr[NN + 4];
__device__ int2  d_es[NE];      // per CSR slot: (edge id, source node)

// ---------------- CSR build ----------------
__global__ void zero_kernel(int n) {
    int i = blockIdx.x * blockDim.x + threadIdx.x;
    if (i < n) { d_deg[i] = 0; d_cur[i] = 0; }
}

__global__ void deg_kernel(const int* __restrict__ tgt, int E) {
    int e = blockIdx.x * blockDim.x + threadIdx.x;
    if (e < E) atomicAdd(&d_deg[tgt[e]], 1);
}

// single-block exclusive scan of d_deg -> d_rowptr, int4-vectorized
__global__ void scan_kernel(int n) {
    __shared__ int ssum[1024];
    int t = threadIdx.x;
    int n4 = n >> 2;
    int C = (n4 + 1023) >> 10;
    int s0 = t * C;
    int s1 = min(s0 + C, n4);
    const int4* deg4 = (const int4*)d_deg;
    int s = 0;
    for (int i = s0; i < s1; i++) {
        int4 v = deg4[i];
        s += v.x + v.y + v.z + v.w;
    }
    ssum[t] = s;
    __syncthreads();
    for (int off = 1; off < 1024; off <<= 1) {
        int v = 0;
        if (t >= off) v = ssum[t - off];
        __syncthreads();
        if (t >= off) ssum[t] += v;
        __syncthreads();
    }
    int run = (t == 0) ? 0 : ssum[t - 1];
    int4* rp4 = (int4*)d_rowptr;
    for (int i = s0; i < s1; i++) {
        int4 v = deg4[i];
        int4 r;
        r.x = run; run += v.x;
        r.y = run; run += v.y;
        r.z = run; run += v.z;
        r.w = run; run += v.w;
        rp4[i] = r;
    }
    if (t == 1023) {
        int run2 = ssum[1023];
        for (int i = n4 * 4; i < n; i++) { d_rowptr[i] = run2; run2 += d_deg[i]; }
        d_rowptr[n] = run2;
    }
}

__global__ void scatter_kernel(const int* __restrict__ src, const int* __restrict__ tgt, int E) {
    int e = blockIdx.x * blockDim.x + threadIdx.x;
    if (e < E) {
        int tg = tgt[e];
        int pos = d_rowptr[tg] + atomicAdd(&d_cur[tg], 1);
        d_es[pos] = make_int2(e, src[e]);
    }
}

// ---------------- fp32 tiled GEMM body (R3-measured form, single buffer) ----------------
__device__ __forceinline__ void gemm_body(const float* __restrict__ A,
                                          const float* __restrict__ B,
                                          const float* __restrict__ bias,
                                          float* __restrict__ C, int M, int bm)
{
    __shared__ float As[8][132];
    __shared__ float Bs[8][128];
    int tid = threadIdx.x;
    int tx = tid & 15;
    int ty = tid >> 4;
    int c0 = tx * 8, r0 = ty * 8;
    float acc[8][8];
#pragma unroll
    for (int i = 0; i < 8; i++)
#pragma unroll
        for (int j = 0; j < 8; j++) acc[i][j] = 0.f;

    int a_row = tid >> 1;
    int a_k   = (tid & 1) * 4;
    int b_k   = tid >> 5;
    int b_c   = (tid & 31) * 4;

    for (int k0 = 0; k0 < 128; k0 += 8) {
        int ar = bm + a_row; if (ar >= M) ar = M - 1;
        float4 av = *(const float4*)(A + (size_t)ar * 128 + k0 + a_k);
        As[a_k + 0][a_row] = av.x;
        As[a_k + 1][a_row] = av.y;
        As[a_k + 2][a_row] = av.z;
        As[a_k + 3][a_row] = av.w;
        float4 bv = *(const float4*)(B + (size_t)(k0 + b_k) * 128 + b_c);
        *(float4*)&Bs[b_k][b_c] = bv;
        __syncthreads();
#pragma unroll
        for (int k = 0; k < 8; k++) {
            float4 a0 = *(const float4*)&As[k][r0];
            float4 a1 = *(const float4*)&As[k][r0 + 4];
            float4 b0 = *(const float4*)&Bs[k][c0];
            float4 b1 = *(const float4*)&Bs[k][c0 + 4];
            float aa[8] = {a0.x, a0.y, a0.z, a0.w, a1.x, a1.y, a1.z, a1.w};
            float bb[8] = {b0.x, b0.y, b0.z, b0.w, b1.x, b1.y, b1.z, b1.w};
#pragma unroll
            for (int i = 0; i < 8; i++)
#pragma unroll
                for (int j = 0; j < 8; j++)
                    acc[i][j] += aa[i] * bb[j];
        }
        __syncthreads();
    }
    float4 bias0 = *(const float4*)(bias + c0);
    float4 bias1 = *(const float4*)(bias + c0 + 4);
    float bb[8] = {bias0.x, bias0.y, bias0.z, bias0.w, bias1.x, bias1.y, bias1.z, bias1.w};
#pragma unroll
    for (int i = 0; i < 8; i++) {
        int row = bm + r0 + i;
        if (row < M) {
            float4 o0 = {acc[i][0] + bb[0], acc[i][1] + bb[1], acc[i][2] + bb[2], acc[i][3] + bb[3]};
            float4 o1 = {acc[i][4] + bb[4], acc[i][5] + bb[5], acc[i][6] + bb[6], acc[i][7] + bb[7]};
            *(float4*)(C + (size_t)row * 128 + c0)     = o0;
            *(float4*)(C + (size_t)row * 128 + c0 + 4) = o1;
        }
    }
}

__global__ void __launch_bounds__(256) gemm_k128(const float* __restrict__ A,
                                                 const float* __restrict__ B,
                                                 const float* __restrict__ bias,
                                                 float* __restrict__ C, int M)
{
    gemm_body(A, B, bias, C, M, blockIdx.x * 128);
}

__global__ void __launch_bounds__(256) gemm_qkv(const float* __restrict__ A,
                                                const float* __restrict__ Wq,
                                                const float* __restrict__ bq,
                                                const float* __restrict__ Wk,
                                                const float* __restrict__ bk,
                                                const float* __restrict__ Wv,
                                                const float* __restrict__ bv,
                                                float* __restrict__ Q,
                                                float* __restrict__ K,
                                                float* __restrict__ V, int M)
{
    const float* B;  const float* bias;  float* C;
    if (blockIdx.y == 0)      { B = Wq; bias = bq; C = Q; }
    else if (blockIdx.y == 1) { B = Wk; bias = bk; C = K; }
    else                      { B = Wv; bias = bv; C = V; }
    gemm_body(A, B, bias, C, M, blockIdx.x * 128);
}

// ---------------- fused per-node attention (warp per node, CSR) ----------------
// Lane layout: lane owns channels [4*lane,4*lane+4) -> head h = lane>>2,
// and edge-feature dims [16*(lane&3), +16). Quad (4 lanes) = one head.
// Edge loop processes 2 edges per iteration: two fully independent dependency
// chains per warp double the memory-level parallelism (the R5 finding: attn is
// chain-latency-bound, not ef-gather-bound).
__global__ void __launch_bounds__(128) attn_kernel(const float* __restrict__ edge_feats,
                                                   const float* __restrict__ Wk,
                                                   const float* __restrict__ Wv,
                                                   int N)
{
    __shared__ float Wve[64 * 128];   // Wv rows 128..191 (edge part), 32 KB
    int tid = threadIdx.x;
    {
        const float4* s2 = (const float4*)(Wv + 128 * 128);
        float4* dst = (float4*)Wve;
        for (int i = tid; i < 2048; i += blockDim.x) dst[i] = s2[i];
    }
    __syncthreads();

    int lane = tid & 31;
    int warp = tid >> 5;
    int cb = lane * 4;
    int h  = lane >> 2;
    int d0 = (lane & 3) * 16;
    int qb = lane & ~3;

    int gw = blockIdx.x * (blockDim.x >> 5) + warp;
    int nw = gridDim.x * (blockDim.x >> 5);

    for (int n = gw; n < N; n += nw) {
        int beg = d_rowptr[n], end = d_rowptr[n + 1];
        float4 q = *(const float4*)(d_Q + (size_t)n * 128 + cb);

        float qh[16];
#pragma unroll
        for (int t = 0; t < 4; t++) {
            qh[4 * t + 0] = __shfl_sync(FULLMASK, q.x, qb + t);
            qh[4 * t + 1] = __shfl_sync(FULLMASK, q.y, qb + t);
            qh[4 * t + 2] = __shfl_sync(FULLMASK, q.z, qb + t);
            qh[4 * t + 3] = __shfl_sync(FULLMASK, q.w, qb + t);
        }
        float U[16];
#pragma unroll
        for (int j = 0; j < 16; j++) {
            const float4* w = (const float4*)(Wk + (size_t)(128 + d0 + j) * 128 + h * 16);
            float4 w0 = w[0], w1 = w[1], w2 = w[2], w3 = w[3];
            U[j] = qh[0]  * w0.x + qh[1]  * w0.y + qh[2]  * w0.z + qh[3]  * w0.w
                 + qh[4]  * w1.x + qh[5]  * w1.y + qh[6]  * w1.z + qh[7]  * w1.w
                 + qh[8]  * w2.x + qh[9]  * w2.y + qh[10] * w2.z + qh[11] * w2.w
                 + qh[12] * w3.x + qh[13] * w3.y + qh[14] * w3.z + qh[15] * w3.w;
        }

        float g[16];
#pragma unroll
        for (int j = 0; j < 16; j++) g[j] = 0.f;
        float o0 = 0.f, o1 = 0.f, o2 = 0.f, o3 = 0.f, sacc = 0.f;

        int idx = beg;
        // --- pair-unrolled main loop: 2 independent edges per iteration ---
        for (; idx + 1 < end; idx += 2) {
            int2 esa = d_es[idx];
            int2 esb = d_es[idx + 1];
            const float4* efa = (const float4*)(edge_feats + (size_t)esa.x * 64 + d0);
            const float4* efb = (const float4*)(edge_feats + (size_t)esb.x * 64 + d0);
            float4 a0 = efa[0], a1 = efa[1], a2 = efa[2], a3 = efa[3];
            float4 b0 = efb[0], b1 = efb[1], b2 = efb[2], b3 = efb[3];
            float4 kna = *(const float4*)(d_Kn + (size_t)esa.y * 128 + cb);
            float4 knb = *(const float4*)(d_Kn + (size_t)esb.y * 128 + cb);
            float4 vna = *(const float4*)(d_Vn + (size_t)esa.y * 128 + cb);
            float4 vnb = *(const float4*)(d_Vn + (size_t)esb.y * 128 + cb);

            float pa = q.x * kna.x + q.y * kna.y + q.z * kna.z + q.w * kna.w;
            float pb = q.x * knb.x + q.y * knb.y + q.z * knb.z + q.w * knb.w;
            pa += a0.x * U[0]  + a0.y * U[1]  + a0.z * U[2]  + a0.w * U[3];
            pb += b0.x * U[0]  + b0.y * U[1]  + b0.z * U[2]  + b0.w * U[3];
            pa += a1.x * U[4]  + a1.y * U[5]  + a1.z * U[6]  + a1.w * U[7];
            pb += b1.x * U[4]  + b1.y * U[5]  + b1.z * U[6]  + b1.w * U[7];
            pa += a2.x * U[8]  + a2.y * U[9]  + a2.z * U[10] + a2.w * U[11];
            pb += b2.x * U[8]  + b2.y * U[9]  + b2.z * U[10] + b2.w * U[11];
            pa += a3.x * U[12] + a3.y * U[13] + a3.z * U[14] + a3.w * U[15];
            pb += b3.x * U[12] + b3.y * U[13] + b3.z * U[14] + b3.w * U[15];
            pa += __shfl_xor_sync(FULLMASK, pa, 1);
            pb += __shfl_xor_sync(FULLMASK, pb, 1);
            pa += __shfl_xor_sync(FULLMASK, pa, 2);
            pb += __shfl_xor_sync(FULLMASK, pb, 2);
            float wa = __expf(0.25f * pa);
            float wb = __expf(0.25f * pb);
            sacc += wa + wb;
            o0 += wa * vna.x + wb * vnb.x;
            o1 += wa * vna.y + wb * vnb.y;
            o2 += wa * vna.z + wb * vnb.z;
            o3 += wa * vna.w + wb * vnb.w;
            g[0]  += wa * a0.x + wb * b0.x; g[1]  += wa * a0.y + wb * b0.y;
            g[2]  += wa * a0.z + wb * b0.z; g[3]  += wa * a0.w + wb * b0.w;
            g[4]  += wa * a1.x + wb * b1.x; g[5]  += wa * a1.y + wb * b1.y;
            g[6]  += wa * a1.z + wb * b1.z; g[7]  += wa * a1.w + wb * b1.w;
            g[8]  += wa * a2.x + wb * b2.x; g[9]  += wa * a2.y + wb * b2.y;
            g[10] += wa * a2.z + wb * b2.z; g[11] += wa * a2.w + wb * b2.w;
            g[12] += wa * a3.x + wb * b3.x; g[13] += wa * a3.y + wb * b3.y;
            g[14] += wa * a3.z + wb * b3.z; g[15] += wa * a3.w + wb * b3.w;
        }
        // --- tail: at most one edge ---
        if (idx < end) {
            int2 es = d_es[idx];
            const float4* ef = (const float4*)(edge_feats + (size_t)es.x * 64 + d0);
            float4 a0 = ef[0], a1 = ef[1], a2 = ef[2], a3 = ef[3];
            float4 kn = *(const float4*)(d_Kn + (size_t)es.y * 128 + cb);
            float4 vn = *(const float4*)(d_Vn + (size_t)es.y * 128 + cb);
            float pa = q.x * kn.x + q.y * kn.y + q.z * kn.z + q.w * kn.w;
            pa += a0.x * U[0]  + a0.y * U[1]  + a0.z * U[2]  + a0.w * U[3];
            pa += a1.x * U[4]  + a1.y * U[5]  + a1.z * U[6]  + a1.w * U[7];
            pa += a2.x * U[8]  + a2.y * U[9]  + a2.z * U[10] + a2.w * U[11];
            pa += a3.x * U[12] + a3.y * U[13] + a3.z * U[14] + a3.w * U[15];
            pa += __shfl_xor_sync(FULLMASK, pa, 1);
            pa += __shfl_xor_sync(FULLMASK, pa, 2);
            float wa = __expf(0.25f * pa);
            sacc += wa;
            o0 += wa * vn.x; o1 += wa * vn.y; o2 += wa * vn.z; o3 += wa * vn.w;
            g[0]  += wa * a0.x; g[1]  += wa * a0.y; g[2]  += wa * a0.z; g[3]  += wa * a0.w;
            g[4]  += wa * a1.x; g[5]  += wa * a1.y; g[6]  += wa * a1.z; g[7]  += wa * a1.w;
            g[8]  += wa * a2.x; g[9]  += wa * a2.y; g[10] += wa * a2.z; g[11] += wa * a2.w;
            g[12] += wa * a3.x; g[13] += wa * a3.y; g[14] += wa * a3.z; g[15] += wa * a3.w;
        }

        // epilogue: o += g @ Wv_e   (g distributed over the quad; exchange via shuffles)
        float ep0 = 0.f, ep1 = 0.f, ep2 = 0.f, ep3 = 0.f;
#pragma unroll
        for (int t = 0; t < 4; t++) {
#pragma unroll
            for (int j = 0; j < 16; j++) {
                float gv = __shfl_sync(FULLMASK, g[j], qb + t);
                float4 w = *(const float4*)(Wve + (size_t)(t * 16 + j) * 128 + cb);
                ep0 += gv * w.x; ep1 += gv * w.y; ep2 += gv * w.z; ep3 += gv * w.w;
            }
        }
        float inv = (sacc > 0.f) ? (1.0f / sacc) : 0.f;
        float4 res;
        res.x = (o0 + ep0) * inv;
        res.y = (o1 + ep1) * inv;
        res.z = (o2 + ep2) * inv;
        res.w = (o3 + ep3) * inv;
        *(float4*)(d_Ov + (size_t)n * 128 + cb) = res;
    }
}

// ---------------- host launcher ----------------
extern "C" void kernel_launch(void* const* d_in, const int* in_sizes, int n_in,
                              void* d_out, int out_size)
{
    const float* node_feats = (const float*)d_in[0];
    const float* edge_feats = (const float*)d_in[1];
    const int*   edge_index = (const int*)  d_in[2];
    const float* Wq = (const float*)d_in[3];
    const float* bq = (const float*)d_in[4];
    const float* Wk = (const float*)d_in[5];
    const float* bk = (const float*)d_in[6];
    const float* Wv = (const float*)d_in[7];
    const float* bv = (const float*)d_in[8];
    const float* Wo = (const float*)d_in[9];
    const float* bo = (const float*)d_in[10];
    float* out = (float*)d_out;

    int N = in_sizes[0] / 128;
    int E = in_sizes[1] / 64;
    const int* src = edge_index;
    const int* tgt = edge_index + E;

    float *pQ, *pKn, *pVn, *pO;
    cudaGetSymbolAddress((void**)&pQ,  d_Q);
    cudaGetSymbolAddress((void**)&pKn, d_Kn);
    cudaGetSymbolAddress((void**)&pVn, d_Vn);
    cudaGetSymbolAddress((void**)&pO,  d_Ov);

    int gblocks = (N + 127) / 128;

    zero_kernel<<<(N + 255) / 256, 256>>>(N);
    gemm_qkv<<<dim3(gblocks, 3), 256>>>(node_feats, Wq, bq, Wk, bk, Wv, bv, pQ, pKn, pVn, N);
    deg_kernel<<<(E + 255) / 256, 256>>>(tgt, E);
    scan_kernel<<<1, 1024>>>(N);
    scatter_kernel<<<(E + 255) / 256, 256>>>(src, tgt, E);
    attn_kernel<<<1776, 128>>>(edge_feats, Wk, Wv, N);
    gemm_k128<<<gblocks, 256>>>(pO, Wo, bo, out, N);
}